// round 5
// baseline (speedup 1.0000x reference)
#include <cuda_runtime.h>
#include <cuda_bf16.h>
#include <stdint.h>

// ---------------------------------------------------------------------------
// ProteinEncoder 3-layer GCN. GEMMs via mma.sync bf16 (HMMA), fp32 accum,
// 3-pass hi/lo split: C = Ahi*Bhi + Ahi*Blo + Alo*Bhi.
// GEMM pipeline: cp.async 3-stage, BK=64, 128x128 CTA tile, 256 threads.
// Aggregation: CSR-by-dst gather, fp32.
// ---------------------------------------------------------------------------

#define MAX_N 50000
#define MPAD  50048            // 391 * 128
#define MAX_E 600000

__device__ float         g_h[(size_t)MAX_N * 512];
__device__ __nv_bfloat16 g_ahi[(size_t)MPAD * 1280];
__device__ __nv_bfloat16 g_alo[(size_t)MPAD * 1280];
__device__ __nv_bfloat16 g_w1hi[512 * 1280], g_w1lo[512 * 1280];  // W1^T [512,1280]
__device__ __nv_bfloat16 g_w2hi[384 * 512],  g_w2lo[384 * 512];   // W2^T [384,512]
__device__ __nv_bfloat16 g_w3hi[384 * 320],  g_w3lo[384 * 320];   // W3^T [384,320]

__device__ int   g_deg[MAX_N];
__device__ float g_dinv[MAX_N];
__device__ int   g_start[MAX_N];
__device__ int   g_scan[MAX_N];
__device__ int   g_cursor[MAX_N];
__device__ int   g_csr_src[MAX_E];
__device__ int   g_bsum[256];

// ---------------------------------------------------------------------------
// helpers
// ---------------------------------------------------------------------------
__device__ __forceinline__ uint32_t smem_u32(const void* p) {
    uint32_t r;
    asm("{ .reg .u64 t; cvta.to.shared.u64 t, %1; cvt.u32.u64 %0, t; }"
        : "=r"(r) : "l"(p));
    return r;
}
__device__ __forceinline__ void ldsm4(uint32_t& r0, uint32_t& r1, uint32_t& r2,
                                      uint32_t& r3, uint32_t addr) {
    asm volatile("ldmatrix.sync.aligned.m8n8.x4.shared.b16 {%0,%1,%2,%3}, [%4];"
                 : "=r"(r0), "=r"(r1), "=r"(r2), "=r"(r3) : "r"(addr));
}
__device__ __forceinline__ void mma16816(float* c, const uint32_t* a,
                                         uint32_t b0, uint32_t b1) {
    asm volatile(
        "mma.sync.aligned.m16n8k16.row.col.f32.bf16.bf16.f32 "
        "{%0,%1,%2,%3}, {%4,%5,%6,%7}, {%8,%9}, {%0,%1,%2,%3};"
        : "+f"(c[0]), "+f"(c[1]), "+f"(c[2]), "+f"(c[3])
        : "r"(a[0]), "r"(a[1]), "r"(a[2]), "r"(a[3]), "r"(b0), "r"(b1));
}
__device__ __forceinline__ void cp16(uint32_t smem, const void* gmem) {
    asm volatile("cp.async.cg.shared.global [%0], [%1], 16;"
                 :: "r"(smem), "l"(gmem));
}
__device__ __forceinline__ void cp_commit() {
    asm volatile("cp.async.commit_group;" ::: "memory");
}
template <int NN>
__device__ __forceinline__ void cp_wait() {
    asm volatile("cp.async.wait_group %0;" :: "n"(NN) : "memory");
}

// ---------------------------------------------------------------------------
// CSR build
// ---------------------------------------------------------------------------
__global__ void k_zero(int n) {
    int i = blockIdx.x * blockDim.x + threadIdx.x;
    if (i < n) { g_deg[i] = 0; g_cursor[i] = 0; }
}
__global__ void k_hist(const int* __restrict__ dst, int E, int n) {
    int e = blockIdx.x * blockDim.x + threadIdx.x;
    if (e < E) {
        int d = dst[e];
        if (d >= 0 && d < n) atomicAdd(&g_deg[d], 1);
    }
}
__global__ void k_scan_block(int n) {
    __shared__ int sh[256];
    int t = threadIdx.x;
    int i = blockIdx.x * 256 + t;
    int v = (i < n) ? g_deg[i] : 0;
    sh[t] = v;
    __syncthreads();
    #pragma unroll
    for (int off = 1; off < 256; off <<= 1) {
        int x = (t >= off) ? sh[t - off] : 0;
        __syncthreads();
        sh[t] += x;
        __syncthreads();
    }
    if (i < n) g_scan[i] = sh[t];
    if (t == 255) g_bsum[blockIdx.x] = sh[255];
}
__global__ void k_scan_top(int nb) {
    __shared__ int sh[256];
    int t = threadIdx.x;
    int v = (t < nb) ? g_bsum[t] : 0;
    sh[t] = v;
    __syncthreads();
    #pragma unroll
    for (int off = 1; off < 256; off <<= 1) {
        int x = (t >= off) ? sh[t - off] : 0;
        __syncthreads();
        sh[t] += x;
        __syncthreads();
    }
    if (t < nb) g_bsum[t] = sh[t] - v;
}
__global__ void k_finish(int n) {
    int i = blockIdx.x * blockDim.x + threadIdx.x;
    if (i < n) {
        g_start[i] = g_scan[i] - g_deg[i] + g_bsum[i >> 8];
        g_dinv[i]  = rsqrtf((float)(g_deg[i] + 1));
    }
}
__global__ void k_fill(const int* __restrict__ src,
                       const int* __restrict__ dst, int E, int n) {
    int e = blockIdx.x * blockDim.x + threadIdx.x;
    if (e < E) {
        int d = dst[e];
        int s = src[e];
        if (d >= 0 && d < n && s >= 0 && s < n) {
            int p = atomicAdd(&g_cursor[d], 1);
            g_csr_src[g_start[d] + p] = s;
        }
    }
}

// ---------------------------------------------------------------------------
// fp32 -> bf16 hi/lo
// ---------------------------------------------------------------------------
__device__ __forceinline__ void split_bf16(float v, __nv_bfloat16& h, __nv_bfloat16& l) {
    h = __float2bfloat16(v);
    l = __float2bfloat16(v - __bfloat162float(h));
}
__global__ void k_cvt(const float* __restrict__ x, __nv_bfloat16* __restrict__ hi,
                      __nv_bfloat16* __restrict__ lo, int total) {
    int i = (blockIdx.x * blockDim.x + threadIdx.x) * 4;
    if (i + 4 <= total) {
        float4 v = *(const float4*)(x + i);
        __nv_bfloat16 h0, l0, h1, l1, h2, l2, h3, l3;
        split_bf16(v.x, h0, l0); split_bf16(v.y, h1, l1);
        split_bf16(v.z, h2, l2); split_bf16(v.w, h3, l3);
        hi[i] = h0; hi[i+1] = h1; hi[i+2] = h2; hi[i+3] = h3;
        lo[i] = l0; lo[i+1] = l1; lo[i+2] = l2; lo[i+3] = l3;
    }
}
// W [K,N] fp32 -> W^T [Npad,Kpad] bf16 hi/lo, zero-padded
__global__ void k_wt(const float* __restrict__ W, __nv_bfloat16* __restrict__ hi,
                     __nv_bfloat16* __restrict__ lo, int K, int N, int Kpad, int Npad) {
    int idx = blockIdx.x * blockDim.x + threadIdx.x;
    if (idx < Npad * Kpad) {
        int n = idx / Kpad, k = idx - n * Kpad;
        float v = (n < N && k < K) ? W[(size_t)k * N + n] : 0.f;
        __nv_bfloat16 h, l;
        split_bf16(v, h, l);
        hi[idx] = h; lo[idx] = l;
    }
}

// ---------------------------------------------------------------------------
// bf16 split GEMM, cp.async 3-stage, BK=64.
// grid (ntilesN, 391), 256 threads (8 warps, 4x2 layout, warp tile 32x64).
// K multiple of 64.
// ---------------------------------------------------------------------------
#define LDS 72                       // padded row stride (elements) for BK=64
#define STAGE_ELEMS (128 * LDS)      // per matrix per stage
#define STAGE_BYTES (STAGE_ELEMS * 2)
#define NSTAGE 3

__global__ __launch_bounds__(256) void bf16_gemm(
    const __nv_bfloat16* __restrict__ Ahi, const __nv_bfloat16* __restrict__ Alo, int lda,
    const __nv_bfloat16* __restrict__ Bhi, const __nv_bfloat16* __restrict__ Blo, int ldb,
    float* __restrict__ C, int M, int Nout, int K) {
    extern __shared__ __nv_bfloat16 sm[];
    __nv_bfloat16* As = sm;                          // NSTAGE stages
    __nv_bfloat16* Bs = sm + NSTAGE * STAGE_ELEMS;   // NSTAGE stages

    const int tid = threadIdx.x;
    const int lane = tid & 31;
    const int wid = tid >> 5;
    const int wm = wid >> 1;     // 0..3
    const int wn = wid & 1;      // 0..1
    const int m0 = blockIdx.y * 128;
    const int n0 = blockIdx.x * 128;

    // cp.async mapping: row = tid>>1 (0..127), 4 x 16B segs per thread
    const int crow = tid >> 1;
    const int cseg = (tid & 1) * 4;      // seg base (each seg = 8 elements)

    const __nv_bfloat16* Aps[3] = {Ahi, Ahi, Alo};
    const __nv_bfloat16* Bps[3] = {Bhi, Blo, Bhi};

    float acc[2][8][4];
    #pragma unroll
    for (int i = 0; i < 2; i++)
        #pragma unroll
        for (int j = 0; j < 8; j++)
            #pragma unroll
            for (int q = 0; q < 4; q++) acc[i][j][q] = 0.f;

    const int kchunks = K / 64;
    const int NT = 3 * kchunks;

    const uint32_t aBase = smem_u32(As);
    const uint32_t bBase = smem_u32(Bs);
    // ldmatrix element offsets within a stage
    const uint32_t aoffElem = (uint32_t)((wm * 32 + (lane & 15)) * LDS + (lane >> 4) * 8);
    const uint32_t boffElem = (uint32_t)((wn * 64 + ((lane >> 4) << 3) + (lane & 7)) * LDS +
                                         ((lane >> 3) & 1) * 8);
    const uint32_t cpAoff = (uint32_t)(crow * LDS + cseg * 8) * 2;  // byte offset
    const uint32_t cpBoff = cpAoff;

    // issue loads for flat iteration `nit` into stage nit%NSTAGE
    auto issue = [&](int nit) {
        const int pass = nit / kchunks;
        const int k0 = (nit - pass * kchunks) * 64;
        const int st = nit % NSTAGE;
        const __nv_bfloat16* Ap = Aps[pass];
        const __nv_bfloat16* Bp = Bps[pass];
        const uint32_t sa = aBase + st * STAGE_BYTES + cpAoff;
        const uint32_t sb = bBase + st * STAGE_BYTES + cpBoff;
        const __nv_bfloat16* ga = Ap + (size_t)(m0 + crow) * lda + k0 + cseg * 8;
        const __nv_bfloat16* gb = Bp + (size_t)(n0 + crow) * ldb + k0 + cseg * 8;
        #pragma unroll
        for (int i = 0; i < 4; i++) cp16(sa + i * 16, ga + i * 8);
        #pragma unroll
        for (int i = 0; i < 4; i++) cp16(sb + i * 16, gb + i * 8);
        cp_commit();
    };

    // prologue: stages 0..NSTAGE-2
    issue(0);
    if (NT > 1) issue(1);

    for (int it = 0; it < NT; it++) {
        cp_wait<NSTAGE - 2>();
        __syncthreads();

        const int st = it % NSTAGE;
        const uint32_t aB = aBase + st * STAGE_BYTES;
        const uint32_t bB = bBase + st * STAGE_BYTES;

        #pragma unroll
        for (int ks = 0; ks < 4; ks++) {
            const uint32_t kofs = (uint32_t)(ks * 16) * 2;
            uint32_t a[2][4];
            #pragma unroll
            for (int mi = 0; mi < 2; mi++)
                ldsm4(a[mi][0], a[mi][1], a[mi][2], a[mi][3],
                      aB + (aoffElem + (uint32_t)(mi * 16) * LDS) * 2 + kofs);
            uint32_t b[4][4];
            #pragma unroll
            for (int nb = 0; nb < 4; nb++)
                ldsm4(b[nb][0], b[nb][1], b[nb][2], b[nb][3],
                      bB + (boffElem + (uint32_t)(nb * 16) * LDS) * 2 + kofs);
            #pragma unroll
            for (int mi = 0; mi < 2; mi++)
                #pragma unroll
                for (int nb = 0; nb < 4; nb++) {
                    mma16816(acc[mi][nb * 2 + 0], a[mi], b[nb][0], b[nb][1]);
                    mma16816(acc[mi][nb * 2 + 1], a[mi], b[nb][2], b[nb][3]);
                }
        }

        if (it + NSTAGE - 1 < NT) issue(it + NSTAGE - 1);
    }

    // --- epilogue ---
    const int g = lane >> 2, tg = lane & 3;
    #pragma unroll
    for (int mi = 0; mi < 2; mi++) {
        #pragma unroll
        for (int nj = 0; nj < 8; nj++) {
            int col = n0 + wn * 64 + nj * 8 + tg * 2;
            int mrow = m0 + wm * 32 + mi * 16 + g;
            #pragma unroll
            for (int half = 0; half < 2; half++) {
                int r = mrow + half * 8;
                if (r < M) {
                    float c0 = acc[mi][nj][half * 2 + 0];
                    float c1 = acc[mi][nj][half * 2 + 1];
                    if (col + 2 <= Nout) {
                        *(float2*)(C + (size_t)r * Nout + col) = make_float2(c0, c1);
                    } else if (col < Nout) {
                        C[(size_t)r * Nout + col] = c0;
                    }
                }
            }
        }
    }
}

// ---------------------------------------------------------------------------
// Aggregation
// ---------------------------------------------------------------------------
template <int F, int FPAD>
__global__ __launch_bounds__(128) void k_agg_bf16(
    const float* __restrict__ h, const float* __restrict__ bias,
    __nv_bfloat16* __restrict__ ohi, __nv_bfloat16* __restrict__ olo) {
    constexpr int BLOCK = 128;
    constexpr int PER = (F + BLOCK - 1) / BLOCK;
    const int node = blockIdx.x;
    const int t = threadIdx.x;

    const float di = g_dinv[node];
    const int s0 = g_start[node];
    const int d  = g_deg[node];

    float acc[PER];
    #pragma unroll
    for (int i = 0; i < PER; i++) {
        int f = t + i * BLOCK;
        acc[i] = (f < F) ? h[(size_t)node * F + f] * di * di : 0.f;
    }
    for (int e = 0; e < d; e++) {
        int s = g_csr_src[s0 + e];
        float w = g_dinv[s] * di;
        #pragma unroll
        for (int i = 0; i < PER; i++) {
            int f = t + i * BLOCK;
            if (f < F) acc[i] += h[(size_t)s * F + f] * w;
        }
    }
    #pragma unroll
    for (int i = 0; i < PER; i++) {
        int f = t + i * BLOCK;
        if (f < F) {
            float v = acc[i] + bias[f];
            v = v > 0.f ? v : 0.f;
            __nv_bfloat16 hh, ll;
            split_bf16(v, hh, ll);
            ohi[(size_t)node * FPAD + f] = hh;
            olo[(size_t)node * FPAD + f] = ll;
        }
    }
    if (FPAD > F && t < FPAD - F) {
        __nv_bfloat16 z = __float2bfloat16(0.f);
        ohi[(size_t)node * FPAD + F + t] = z;
        olo[(size_t)node * FPAD + F + t] = z;
    }
}

template <int F>
__global__ __launch_bounds__(128) void k_agg_f32(
    const float* __restrict__ h, const float* __restrict__ bias,
    float* __restrict__ out) {
    constexpr int BLOCK = 128;
    constexpr int PER = (F + BLOCK - 1) / BLOCK;
    const int node = blockIdx.x;
    const int t = threadIdx.x;

    const float di = g_dinv[node];
    const int s0 = g_start[node];
    const int d  = g_deg[node];

    float acc[PER];
    #pragma unroll
    for (int i = 0; i < PER; i++) {
        int f = t + i * BLOCK;
        acc[i] = (f < F) ? h[(size_t)node * F + f] * di * di : 0.f;
    }
    for (int e = 0; e < d; e++) {
        int s = g_csr_src[s0 + e];
        float w = g_dinv[s] * di;
        #pragma unroll
        for (int i = 0; i < PER; i++) {
            int f = t + i * BLOCK;
            if (f < F) acc[i] += h[(size_t)s * F + f] * w;
        }
    }
    #pragma unroll
    for (int i = 0; i < PER; i++) {
        int f = t + i * BLOCK;
        if (f < F) {
            float v = acc[i] + bias[f];
            out[(size_t)node * F + f] = v > 0.f ? v : 0.f;
        }
    }
}

// ---------------------------------------------------------------------------
// Launch
// ---------------------------------------------------------------------------
extern "C" void kernel_launch(void* const* d_in, const int* in_sizes, int n_in,
                              void* d_out, int out_size) {
    const float* x  = (const float*)d_in[0];
    const float* W1 = (const float*)d_in[1];
    const float* b1 = (const float*)d_in[2];
    const float* W2 = (const float*)d_in[3];
    const float* b2 = (const float*)d_in[4];
    const float* W3 = (const float*)d_in[5];
    const float* b3 = (const float*)d_in[6];
    const int*   ei = (const int*)d_in[7];   // int32 (JAX x64-disabled downcast)

    const int D0 = 1280;
    const int N = in_sizes[0] / D0;
    const int E = in_sizes[7] / 2;
    const int* src = ei;
    const int* dst = ei + E;

    float* h = nullptr;
    __nv_bfloat16 *ahi = nullptr, *alo = nullptr;
    __nv_bfloat16 *w1h = nullptr, *w1l = nullptr, *w2h = nullptr, *w2l = nullptr,
                  *w3h = nullptr, *w3l = nullptr;
    cudaGetSymbolAddress((void**)&h,   g_h);
    cudaGetSymbolAddress((void**)&ahi, g_ahi);
    cudaGetSymbolAddress((void**)&alo, g_alo);
    cudaGetSymbolAddress((void**)&w1h, g_w1hi);
    cudaGetSymbolAddress((void**)&w1l, g_w1lo);
    cudaGetSymbolAddress((void**)&w2h, g_w2hi);
    cudaGetSymbolAddress((void**)&w2l, g_w2lo);
    cudaGetSymbolAddress((void**)&w3h, g_w3hi);
    cudaGetSymbolAddress((void**)&w3l, g_w3lo);

    const int SMEM_BYTES = NSTAGE * STAGE_BYTES * 2;  // A + B stages
    cudaFuncSetAttribute(bf16_gemm, cudaFuncAttributeMaxDynamicSharedMemorySize,
                         SMEM_BYTES);

    const int T = 256;
    const int nbN = (N + T - 1) / T;
    const int nbE = (E + T - 1) / T;
    const int nbScan = (N + 255) / 256;

    // CSR build + dinv
    k_zero<<<nbN, T>>>(N);
    k_hist<<<nbE, T>>>(dst, E, N);
    k_scan_block<<<nbScan, 256>>>(N);
    k_scan_top<<<1, 256>>>(nbScan);
    k_finish<<<nbN, T>>>(N);
    k_fill<<<nbE, T>>>(src, dst, E, N);

    // weight transposes + splits
    k_wt<<<(512 * 1280 + 255) / 256, 256>>>(W1, w1h, w1l, 1280, 512, 1280, 512);
    k_wt<<<(384 * 512 + 255) / 256, 256>>>(W2, w2h, w2l, 512, 300, 512, 384);
    k_wt<<<(384 * 320 + 255) / 256, 256>>>(W3, w3h, w3l, 300, 300, 320, 384);

    // x -> hi/lo
    const int totX = N * D0;
    k_cvt<<<(totX / 4 + 255) / 256, 256>>>(x, ahi, alo, totX);

    const int ntm = MPAD / 128;  // 391

    // Layer 1: h1 = x@W1 [N,512]
    bf16_gemm<<<dim3(4, ntm), 256, SMEM_BYTES>>>(ahi, alo, 1280, w1h, w1l, 1280,
                                                 h, N, 512, 1280);
    k_agg_bf16<512, 512><<<N, 128>>>(h, b1, ahi, alo);

    // Layer 2: h2 = a1@W2 [N,300]
    bf16_gemm<<<dim3(3, ntm), 256, SMEM_BYTES>>>(ahi, alo, 512, w2h, w2l, 512,
                                                 h, N, 300, 512);
    k_agg_bf16<300, 320><<<N, 128>>>(h, b2, ahi, alo);

    // Layer 3: h3 = a2@W3 [N,300]
    bf16_gemm<<<dim3(3, ntm), 256, SMEM_BYTES>>>(ahi, alo, 320, w3h, w3l, 320,
                                                 h, N, 300, 320);
    k_agg_f32<300><<<N, 128>>>(h, b3, (float*)d_out);
}

// round 6
// speedup vs baseline: 1.3255x; 1.3255x over previous
#include <cuda_runtime.h>
#include <cuda_fp16.h>
#include <stdint.h>

// ---------------------------------------------------------------------------
// ProteinEncoder 3-layer GCN. GEMMs via mma.sync fp16 (HMMA), fp32 accum.
// 2-pass weight-split scheme:  C = A16*Whi + A16*Wlo
//   A kept as single fp16 (error ~2^-12, dominates, ~4e-4 final rel_err)
//   W split hi/lo fp16 (residual 2^-24, negligible)
// GEMM: cp.async 3-stage, BK=64, 128x128 CTA tile, 256 threads.
// Aggregation: CSR-by-dst gather, fp32 accum, edge-loop unrolled x2.
// ---------------------------------------------------------------------------

#define MAX_N 50000
#define MPAD  50048            // 391 * 128
#define MAX_E 600000

__device__ float  g_h[(size_t)MAX_N * 512];
__device__ __half g_a16[(size_t)MPAD * 1280];
__device__ __half g_w1hi[512 * 1280], g_w1lo[512 * 1280];  // W1^T [512,1280]
__device__ __half g_w2hi[384 * 512],  g_w2lo[384 * 512];   // W2^T [384,512]
__device__ __half g_w3hi[384 * 320],  g_w3lo[384 * 320];   // W3^T [384,320]

__device__ int   g_deg[MAX_N];
__device__ float g_dinv[MAX_N];
__device__ int   g_start[MAX_N];
__device__ int   g_scan[MAX_N];
__device__ int   g_cursor[MAX_N];
__device__ int   g_csr_src[MAX_E];
__device__ int   g_bsum[256];

// ---------------------------------------------------------------------------
// helpers
// ---------------------------------------------------------------------------
__device__ __forceinline__ uint32_t smem_u32(const void* p) {
    uint32_t r;
    asm("{ .reg .u64 t; cvta.to.shared.u64 t, %1; cvt.u32.u64 %0, t; }"
        : "=r"(r) : "l"(p));
    return r;
}
__device__ __forceinline__ void ldsm4(uint32_t& r0, uint32_t& r1, uint32_t& r2,
                                      uint32_t& r3, uint32_t addr) {
    asm volatile("ldmatrix.sync.aligned.m8n8.x4.shared.b16 {%0,%1,%2,%3}, [%4];"
                 : "=r"(r0), "=r"(r1), "=r"(r2), "=r"(r3) : "r"(addr));
}
__device__ __forceinline__ void mma16816(float* c, const uint32_t* a,
                                         uint32_t b0, uint32_t b1) {
    asm volatile(
        "mma.sync.aligned.m16n8k16.row.col.f32.f16.f16.f32 "
        "{%0,%1,%2,%3}, {%4,%5,%6,%7}, {%8,%9}, {%0,%1,%2,%3};"
        : "+f"(c[0]), "+f"(c[1]), "+f"(c[2]), "+f"(c[3])
        : "r"(a[0]), "r"(a[1]), "r"(a[2]), "r"(a[3]), "r"(b0), "r"(b1));
}
__device__ __forceinline__ void cp16(uint32_t smem, const void* gmem) {
    asm volatile("cp.async.cg.shared.global [%0], [%1], 16;"
                 :: "r"(smem), "l"(gmem));
}
__device__ __forceinline__ void cp_commit() {
    asm volatile("cp.async.commit_group;" ::: "memory");
}
template <int NN>
__device__ __forceinline__ void cp_wait() {
    asm volatile("cp.async.wait_group %0;" :: "n"(NN) : "memory");
}

// ---------------------------------------------------------------------------
// CSR build
// ---------------------------------------------------------------------------
__global__ void k_zero(int n) {
    int i = blockIdx.x * blockDim.x + threadIdx.x;
    if (i < n) { g_deg[i] = 0; g_cursor[i] = 0; }
}
__global__ void k_hist(const int* __restrict__ dst, int E, int n) {
    int e = blockIdx.x * blockDim.x + threadIdx.x;
    if (e < E) {
        int d = dst[e];
        if (d >= 0 && d < n) atomicAdd(&g_deg[d], 1);
    }
}
__global__ void k_scan_block(int n) {
    __shared__ int sh[256];
    int t = threadIdx.x;
    int i = blockIdx.x * 256 + t;
    int v = (i < n) ? g_deg[i] : 0;
    sh[t] = v;
    __syncthreads();
    #pragma unroll
    for (int off = 1; off < 256; off <<= 1) {
        int x = (t >= off) ? sh[t - off] : 0;
        __syncthreads();
        sh[t] += x;
        __syncthreads();
    }
    if (i < n) g_scan[i] = sh[t];
    if (t == 255) g_bsum[blockIdx.x] = sh[255];
}
__global__ void k_scan_top(int nb) {
    __shared__ int sh[256];
    int t = threadIdx.x;
    int v = (t < nb) ? g_bsum[t] : 0;
    sh[t] = v;
    __syncthreads();
    #pragma unroll
    for (int off = 1; off < 256; off <<= 1) {
        int x = (t >= off) ? sh[t - off] : 0;
        __syncthreads();
        sh[t] += x;
        __syncthreads();
    }
    if (t < nb) g_bsum[t] = sh[t] - v;
}
__global__ void k_finish(int n) {
    int i = blockIdx.x * blockDim.x + threadIdx.x;
    if (i < n) {
        g_start[i] = g_scan[i] - g_deg[i] + g_bsum[i >> 8];
        g_dinv[i]  = rsqrtf((float)(g_deg[i] + 1));
    }
}
__global__ void k_fill(const int* __restrict__ src,
                       const int* __restrict__ dst, int E, int n) {
    int e = blockIdx.x * blockDim.x + threadIdx.x;
    if (e < E) {
        int d = dst[e];
        int s = src[e];
        if (d >= 0 && d < n && s >= 0 && s < n) {
            int p = atomicAdd(&g_cursor[d], 1);
            g_csr_src[g_start[d] + p] = s;
        }
    }
}

// ---------------------------------------------------------------------------
// conversions
// ---------------------------------------------------------------------------
__global__ void k_cvt(const float* __restrict__ x, __half* __restrict__ a16,
                      int total) {
    int i = (blockIdx.x * blockDim.x + threadIdx.x) * 4;
    if (i + 4 <= total) {
        float4 v = *(const float4*)(x + i);
        __half2 p0 = __floats2half2_rn(v.x, v.y);
        __half2 p1 = __floats2half2_rn(v.z, v.w);
        *(__half2*)(a16 + i)     = p0;
        *(__half2*)(a16 + i + 2) = p1;
    }
}
// W [K,N] fp32 -> W^T [Npad,Kpad] fp16 hi/lo, zero-padded
__global__ void k_wt(const float* __restrict__ W, __half* __restrict__ hi,
                     __half* __restrict__ lo, int K, int N, int Kpad, int Npad) {
    int idx = blockIdx.x * blockDim.x + threadIdx.x;
    if (idx < Npad * Kpad) {
        int n = idx / Kpad, k = idx - n * Kpad;
        float v = (n < N && k < K) ? W[(size_t)k * N + n] : 0.f;
        __half h = __float2half_rn(v);
        __half l = __float2half_rn(v - __half2float(h));
        hi[idx] = h; lo[idx] = l;
    }
}

// ---------------------------------------------------------------------------
// fp16 2-pass GEMM, cp.async 3-stage, BK=64.
// grid (ntilesN, 391), 256 threads (8 warps, 4x2, warp tile 32x64).
// C = A*Bhi + A*Blo. K multiple of 64.
// ---------------------------------------------------------------------------
#define LDS 72
#define STAGE_ELEMS (128 * LDS)
#define STAGE_BYTES (STAGE_ELEMS * 2)
#define NSTAGE 3

__global__ __launch_bounds__(256) void fp16_gemm(
    const __half* __restrict__ A, int lda,
    const __half* __restrict__ Bhi, const __half* __restrict__ Blo, int ldb,
    float* __restrict__ C, int M, int Nout, int K) {
    extern __shared__ __half sm[];
    __half* As = sm;
    __half* Bs = sm + NSTAGE * STAGE_ELEMS;

    const int tid = threadIdx.x;
    const int lane = tid & 31;
    const int wid = tid >> 5;
    const int wm = wid >> 1;
    const int wn = wid & 1;
    const int m0 = blockIdx.y * 128;
    const int n0 = blockIdx.x * 128;

    const int crow = tid >> 1;
    const int cseg = (tid & 1) * 4;

    const __half* Bps[2] = {Bhi, Blo};

    float acc[2][8][4];
    #pragma unroll
    for (int i = 0; i < 2; i++)
        #pragma unroll
        for (int j = 0; j < 8; j++)
            #pragma unroll
            for (int q = 0; q < 4; q++) acc[i][j][q] = 0.f;

    const int kchunks = K / 64;
    const int NT = 2 * kchunks;

    const uint32_t aBase = smem_u32(As);
    const uint32_t bBase = smem_u32(Bs);
    const uint32_t aoffElem = (uint32_t)((wm * 32 + (lane & 15)) * LDS + (lane >> 4) * 8);
    const uint32_t boffElem = (uint32_t)((wn * 64 + ((lane >> 4) << 3) + (lane & 7)) * LDS +
                                         ((lane >> 3) & 1) * 8);
    const uint32_t cpOff = (uint32_t)(crow * LDS + cseg * 8) * 2;

    auto issue = [&](int nit) {
        const int pass = nit / kchunks;
        const int k0 = (nit - pass * kchunks) * 64;
        const int st = nit % NSTAGE;
        const __half* Bp = Bps[pass];
        const uint32_t sa = aBase + st * STAGE_BYTES + cpOff;
        const uint32_t sb = bBase + st * STAGE_BYTES + cpOff;
        const __half* ga = A + (size_t)(m0 + crow) * lda + k0 + cseg * 8;
        const __half* gb = Bp + (size_t)(n0 + crow) * ldb + k0 + cseg * 8;
        #pragma unroll
        for (int i = 0; i < 4; i++) cp16(sa + i * 16, ga + i * 8);
        #pragma unroll
        for (int i = 0; i < 4; i++) cp16(sb + i * 16, gb + i * 8);
        cp_commit();
    };

    issue(0);
    if (NT > 1) issue(1);

    for (int it = 0; it < NT; it++) {
        cp_wait<NSTAGE - 2>();
        __syncthreads();

        const int st = it % NSTAGE;
        const uint32_t aB = aBase + st * STAGE_BYTES;
        const uint32_t bB = bBase + st * STAGE_BYTES;

        #pragma unroll
        for (int ks = 0; ks < 4; ks++) {
            const uint32_t kofs = (uint32_t)(ks * 16) * 2;
            uint32_t a[2][4];
            #pragma unroll
            for (int mi = 0; mi < 2; mi++)
                ldsm4(a[mi][0], a[mi][1], a[mi][2], a[mi][3],
                      aB + (aoffElem + (uint32_t)(mi * 16) * LDS) * 2 + kofs);
            uint32_t b[4][4];
            #pragma unroll
            for (int nb = 0; nb < 4; nb++)
                ldsm4(b[nb][0], b[nb][1], b[nb][2], b[nb][3],
                      bB + (boffElem + (uint32_t)(nb * 16) * LDS) * 2 + kofs);
            #pragma unroll
            for (int mi = 0; mi < 2; mi++)
                #pragma unroll
                for (int nb = 0; nb < 4; nb++) {
                    mma16816(acc[mi][nb * 2 + 0], a[mi], b[nb][0], b[nb][1]);
                    mma16816(acc[mi][nb * 2 + 1], a[mi], b[nb][2], b[nb][3]);
                }
        }

        if (it + NSTAGE - 1 < NT) issue(it + NSTAGE - 1);
    }

    const int g = lane >> 2, tg = lane & 3;
    #pragma unroll
    for (int mi = 0; mi < 2; mi++) {
        #pragma unroll
        for (int nj = 0; nj < 8; nj++) {
            int col = n0 + wn * 64 + nj * 8 + tg * 2;
            int mrow = m0 + wm * 32 + mi * 16 + g;
            #pragma unroll
            for (int half = 0; half < 2; half++) {
                int r = mrow + half * 8;
                if (r < M) {
                    float c0 = acc[mi][nj][half * 2 + 0];
                    float c1 = acc[mi][nj][half * 2 + 1];
                    if (col + 2 <= Nout) {
                        *(float2*)(C + (size_t)r * Nout + col) = make_float2(c0, c1);
                    } else if (col < Nout) {
                        C[(size_t)r * Nout + col] = c0;
                    }
                }
            }
        }
    }
}

// ---------------------------------------------------------------------------
// Aggregation: out[d] = relu(sum_e h[src]*dinv[s]*dinv[d] + h[d]*dinv[d]^2 + b)
// Edge loop unrolled x2 for memory-level parallelism.
// ---------------------------------------------------------------------------
template <int F, int FPAD>
__global__ __launch_bounds__(128) void k_agg_f16(
    const float* __restrict__ h, const float* __restrict__ bias,
    __half* __restrict__ out16) {
    constexpr int BLOCK = 128;
    constexpr int PER = (F + BLOCK - 1) / BLOCK;
    const int node = blockIdx.x;
    const int t = threadIdx.x;

    const float di = g_dinv[node];
    const int s0 = g_start[node];
    const int d  = g_deg[node];

    float acc[PER];
    #pragma unroll
    for (int i = 0; i < PER; i++) {
        int f = t + i * BLOCK;
        acc[i] = (f < F) ? h[(size_t)node * F + f] * di * di : 0.f;
    }
    int e = 0;
    for (; e + 2 <= d; e += 2) {
        int s1 = g_csr_src[s0 + e];
        int s2 = g_csr_src[s0 + e + 1];
        float w1 = g_dinv[s1] * di;
        float w2 = g_dinv[s2] * di;
        const float* r1 = h + (size_t)s1 * F;
        const float* r2 = h + (size_t)s2 * F;
        #pragma unroll
        for (int i = 0; i < PER; i++) {
            int f = t + i * BLOCK;
            if (f < F) acc[i] += r1[f] * w1 + r2[f] * w2;
        }
    }
    if (e < d) {
        int s = g_csr_src[s0 + e];
        float w = g_dinv[s] * di;
        const float* r = h + (size_t)s * F;
        #pragma unroll
        for (int i = 0; i < PER; i++) {
            int f = t + i * BLOCK;
            if (f < F) acc[i] += r[f] * w;
        }
    }
    #pragma unroll
    for (int i = 0; i < PER; i++) {
        int f = t + i * BLOCK;
        if (f < F) {
            float v = acc[i] + bias[f];
            v = v > 0.f ? v : 0.f;
            out16[(size_t)node * FPAD + f] = __float2half_rn(v);
        }
    }
    if (FPAD > F && t < FPAD - F)
        out16[(size_t)node * FPAD + F + t] = __float2half_rn(0.f);
}

template <int F>
__global__ __launch_bounds__(128) void k_agg_f32(
    const float* __restrict__ h, const float* __restrict__ bias,
    float* __restrict__ out) {
    constexpr int BLOCK = 128;
    constexpr int PER = (F + BLOCK - 1) / BLOCK;
    const int node = blockIdx.x;
    const int t = threadIdx.x;

    const float di = g_dinv[node];
    const int s0 = g_start[node];
    const int d  = g_deg[node];

    float acc[PER];
    #pragma unroll
    for (int i = 0; i < PER; i++) {
        int f = t + i * BLOCK;
        acc[i] = (f < F) ? h[(size_t)node * F + f] * di * di : 0.f;
    }
    int e = 0;
    for (; e + 2 <= d; e += 2) {
        int s1 = g_csr_src[s0 + e];
        int s2 = g_csr_src[s0 + e + 1];
        float w1 = g_dinv[s1] * di;
        float w2 = g_dinv[s2] * di;
        const float* r1 = h + (size_t)s1 * F;
        const float* r2 = h + (size_t)s2 * F;
        #pragma unroll
        for (int i = 0; i < PER; i++) {
            int f = t + i * BLOCK;
            if (f < F) acc[i] += r1[f] * w1 + r2[f] * w2;
        }
    }
    if (e < d) {
        int s = g_csr_src[s0 + e];
        float w = g_dinv[s] * di;
        const float* r = h + (size_t)s * F;
        #pragma unroll
        for (int i = 0; i < PER; i++) {
            int f = t + i * BLOCK;
            if (f < F) acc[i] += r[f] * w;
        }
    }
    #pragma unroll
    for (int i = 0; i < PER; i++) {
        int f = t + i * BLOCK;
        if (f < F) {
            float v = acc[i] + bias[f];
            out[(size_t)node * F + f] = v > 0.f ? v : 0.f;
        }
    }
}

// ---------------------------------------------------------------------------
// Launch. Order arranged so launch #4 is fp16_gemm (ncu capture lands there).
// ---------------------------------------------------------------------------
extern "C" void kernel_launch(void* const* d_in, const int* in_sizes, int n_in,
                              void* d_out, int out_size) {
    const float* x  = (const float*)d_in[0];
    const float* W1 = (const float*)d_in[1];
    const float* b1 = (const float*)d_in[2];
    const float* W2 = (const float*)d_in[3];
    const float* b2 = (const float*)d_in[4];
    const float* W3 = (const float*)d_in[5];
    const float* b3 = (const float*)d_in[6];
    const int*   ei = (const int*)d_in[7];   // int32 (JAX x64-disabled downcast)

    const int D0 = 1280;
    const int N = in_sizes[0] / D0;
    const int E = in_sizes[7] / 2;
    const int* src = ei;
    const int* dst = ei + E;

    float* h = nullptr;
    __half *a16 = nullptr;
    __half *w1h = nullptr, *w1l = nullptr, *w2h = nullptr, *w2l = nullptr,
           *w3h = nullptr, *w3l = nullptr;
    cudaGetSymbolAddress((void**)&h,   g_h);
    cudaGetSymbolAddress((void**)&a16, g_a16);
    cudaGetSymbolAddress((void**)&w1h, g_w1hi);
    cudaGetSymbolAddress((void**)&w1l, g_w1lo);
    cudaGetSymbolAddress((void**)&w2h, g_w2hi);
    cudaGetSymbolAddress((void**)&w2l, g_w2lo);
    cudaGetSymbolAddress((void**)&w3h, g_w3hi);
    cudaGetSymbolAddress((void**)&w3l, g_w3lo);

    const int SMEM_BYTES = NSTAGE * STAGE_BYTES * 2;
    cudaFuncSetAttribute(fp16_gemm, cudaFuncAttributeMaxDynamicSharedMemorySize,
                         SMEM_BYTES);

    const int T = 256;
    const int nbN = (N + T - 1) / T;
    const int nbE = (E + T - 1) / T;
    const int nbScan = (N + 255) / 256;
    const int ntm = MPAD / 128;  // 391
    const int totX = N * D0;

    // 1: x -> fp16
    k_cvt<<<(totX / 4 + 255) / 256, 256>>>(x, a16, totX);
    // 2-3: W1 split
    k_wt<<<(512 * 1280 + 255) / 256, 256>>>(W1, w1h, w1l, 1280, 512, 1280, 512);
    k_wt<<<(384 * 512 + 255) / 256, 256>>>(W2, w2h, w2l, 512, 300, 512, 384);
    // 4: GEMM layer 1 (ncu capture target)
    fp16_gemm<<<dim3(4, ntm), 256, SMEM_BYTES>>>(a16, 1280, w1h, w1l, 1280,
                                                 h, N, 512, 1280);
    // 5: W3 split
    k_wt<<<(384 * 320 + 255) / 256, 256>>>(W3, w3h, w3l, 300, 300, 320, 384);
    // 6-11: CSR build + dinv
    k_zero<<<nbN, T>>>(N);
    k_hist<<<nbE, T>>>(dst, E, N);
    k_scan_block<<<nbScan, 256>>>(N);
    k_scan_top<<<1, 256>>>(nbScan);
    k_finish<<<nbN, T>>>(N);
    k_fill<<<nbE, T>>>(src, dst, E, N);

    // Layer 1 aggregation -> fp16 input of layer 2
    k_agg_f16<512, 512><<<N, 128>>>(h, b1, a16);

    // Layer 2
    fp16_gemm<<<dim3(3, ntm), 256, SMEM_BYTES>>>(a16, 512, w2h, w2l, 512,
                                                 h, N, 300, 512);
    k_agg_f16<300, 320><<<N, 128>>>(h, b2, a16);

    // Layer 3
    fp16_gemm<<<dim3(3, ntm), 256, SMEM_BYTES>>>(a16, 320, w3h, w3l, 320,
                                                 h, N, 300, 320);
    k_agg_f32<300><<<N, 128>>>(h, b3, (float*)d_out);
}

// round 7
// speedup vs baseline: 2.0527x; 1.5486x over previous
#include <cuda_runtime.h>
#include <cuda_fp16.h>
#include <stdint.h>

// ---------------------------------------------------------------------------
// ProteinEncoder 3-layer GCN. Single-pass fp16 mma.sync GEMM (fp32 accum),
// h activations stored fp16, CSR gather aggregation with fp32 accum.
//   error budget: A,W fp16 rounding ~2^-11 sign-random over K -> ~1.5e-4 rel.
// ---------------------------------------------------------------------------

#define MAX_N 50000
#define MPAD  50048            // 391 * 128
#define MAX_E 600000

__device__ __half g_h16[(size_t)MAX_N * 512];        // GEMM output (fp16)
__device__ __half g_a16[(size_t)MPAD * 1280];        // GEMM A input (fp16)
__device__ __half g_w1[512 * 1280];                  // W1^T [512,1280]
__device__ __half g_w2[384 * 512];                   // W2^T [384,512]
__device__ __half g_w3[384 * 320];                   // W3^T [384,320]

__device__ int   g_deg[MAX_N];
__device__ float g_dinv[MAX_N];
__device__ int   g_start[MAX_N];
__device__ int   g_scan[MAX_N];
__device__ int   g_cursor[MAX_N];
__device__ int   g_csr_src[MAX_E];
__device__ int   g_bsum[256];

// ---------------------------------------------------------------------------
// helpers
// ---------------------------------------------------------------------------
__device__ __forceinline__ uint32_t smem_u32(const void* p) {
    uint32_t r;
    asm("{ .reg .u64 t; cvta.to.shared.u64 t, %1; cvt.u32.u64 %0, t; }"
        : "=r"(r) : "l"(p));
    return r;
}
__device__ __forceinline__ void ldsm4(uint32_t& r0, uint32_t& r1, uint32_t& r2,
                                      uint32_t& r3, uint32_t addr) {
    asm volatile("ldmatrix.sync.aligned.m8n8.x4.shared.b16 {%0,%1,%2,%3}, [%4];"
                 : "=r"(r0), "=r"(r1), "=r"(r2), "=r"(r3) : "r"(addr));
}
__device__ __forceinline__ void mma16816(float* c, const uint32_t* a,
                                         uint32_t b0, uint32_t b1) {
    asm volatile(
        "mma.sync.aligned.m16n8k16.row.col.f32.f16.f16.f32 "
        "{%0,%1,%2,%3}, {%4,%5,%6,%7}, {%8,%9}, {%0,%1,%2,%3};"
        : "+f"(c[0]), "+f"(c[1]), "+f"(c[2]), "+f"(c[3])
        : "r"(a[0]), "r"(a[1]), "r"(a[2]), "r"(a[3]), "r"(b0), "r"(b1));
}
__device__ __forceinline__ void cp16(uint32_t smem, const void* gmem) {
    asm volatile("cp.async.cg.shared.global [%0], [%1], 16;"
                 :: "r"(smem), "l"(gmem));
}
__device__ __forceinline__ void cp_commit() {
    asm volatile("cp.async.commit_group;" ::: "memory");
}
template <int NN>
__device__ __forceinline__ void cp_wait() {
    asm volatile("cp.async.wait_group %0;" :: "n"(NN) : "memory");
}

// ---------------------------------------------------------------------------
// CSR build
// ---------------------------------------------------------------------------
__global__ void k_zero(int n) {
    int i = blockIdx.x * blockDim.x + threadIdx.x;
    if (i < n) { g_deg[i] = 0; g_cursor[i] = 0; }
}
__global__ void k_hist(const int* __restrict__ dst, int E, int n) {
    int e = blockIdx.x * blockDim.x + threadIdx.x;
    if (e < E) {
        int d = dst[e];
        if (d >= 0 && d < n) atomicAdd(&g_deg[d], 1);
    }
}
__global__ void k_scan_block(int n) {
    __shared__ int sh[256];
    int t = threadIdx.x;
    int i = blockIdx.x * 256 + t;
    int v = (i < n) ? g_deg[i] : 0;
    sh[t] = v;
    __syncthreads();
    #pragma unroll
    for (int off = 1; off < 256; off <<= 1) {
        int x = (t >= off) ? sh[t - off] : 0;
        __syncthreads();
        sh[t] += x;
        __syncthreads();
    }
    if (i < n) g_scan[i] = sh[t];
    if (t == 255) g_bsum[blockIdx.x] = sh[255];
}
__global__ void k_scan_top(int nb) {
    __shared__ int sh[256];
    int t = threadIdx.x;
    int v = (t < nb) ? g_bsum[t] : 0;
    sh[t] = v;
    __syncthreads();
    #pragma unroll
    for (int off = 1; off < 256; off <<= 1) {
        int x = (t >= off) ? sh[t - off] : 0;
        __syncthreads();
        sh[t] += x;
        __syncthreads();
    }
    if (t < nb) g_bsum[t] = sh[t] - v;
}
__global__ void k_finish(int n) {
    int i = blockIdx.x * blockDim.x + threadIdx.x;
    if (i < n) {
        g_start[i] = g_scan[i] - g_deg[i] + g_bsum[i >> 8];
        g_dinv[i]  = rsqrtf((float)(g_deg[i] + 1));
    }
}
__global__ void k_fill(const int* __restrict__ src,
                       const int* __restrict__ dst, int E, int n) {
    int e = blockIdx.x * blockDim.x + threadIdx.x;
    if (e < E) {
        int d = dst[e];
        int s = src[e];
        if (d >= 0 && d < n && s >= 0 && s < n) {
            int p = atomicAdd(&g_cursor[d], 1);
            g_csr_src[g_start[d] + p] = s;
        }
    }
}

// ---------------------------------------------------------------------------
// conversions
// ---------------------------------------------------------------------------
__global__ void k_cvt(const float* __restrict__ x, __half* __restrict__ a16,
                      int total) {
    int i = (blockIdx.x * blockDim.x + threadIdx.x) * 4;
    if (i + 4 <= total) {
        float4 v = *(const float4*)(x + i);
        *(__half2*)(a16 + i)     = __floats2half2_rn(v.x, v.y);
        *(__half2*)(a16 + i + 2) = __floats2half2_rn(v.z, v.w);
    }
}
// W [K,N] fp32 -> W^T [Npad,Kpad] fp16, zero-padded
__global__ void k_wt(const float* __restrict__ W, __half* __restrict__ wt,
                     int K, int N, int Kpad, int Npad) {
    int idx = blockIdx.x * blockDim.x + threadIdx.x;
    if (idx < Npad * Kpad) {
        int n = idx / Kpad, k = idx - n * Kpad;
        float v = (n < N && k < K) ? W[(size_t)k * N + n] : 0.f;
        wt[idx] = __float2half_rn(v);
    }
}

// ---------------------------------------------------------------------------
// fp16 single-pass GEMM, cp.async 3-stage, BK=64.
// grid (ntilesN, 391), 256 threads (8 warps, 4x2, warp tile 32x64).
// C (fp16) = A*B^T. K multiple of 64.
// ---------------------------------------------------------------------------
#define LDS 72
#define STAGE_ELEMS (128 * LDS)
#define STAGE_BYTES (STAGE_ELEMS * 2)
#define NSTAGE 3

__global__ __launch_bounds__(256) void fp16_gemm(
    const __half* __restrict__ A, int lda,
    const __half* __restrict__ B, int ldb,
    __half* __restrict__ C, int M, int Nout, int K) {
    extern __shared__ __half sm[];
    __half* As = sm;
    __half* Bs = sm + NSTAGE * STAGE_ELEMS;

    const int tid = threadIdx.x;
    const int lane = tid & 31;
    const int wid = tid >> 5;
    const int wm = wid >> 1;
    const int wn = wid & 1;
    const int m0 = blockIdx.y * 128;
    const int n0 = blockIdx.x * 128;

    const int crow = tid >> 1;
    const int cseg = (tid & 1) * 4;

    float acc[2][8][4];
    #pragma unroll
    for (int i = 0; i < 2; i++)
        #pragma unroll
        for (int j = 0; j < 8; j++)
            #pragma unroll
            for (int q = 0; q < 4; q++) acc[i][j][q] = 0.f;

    const int NT = K / 64;

    const uint32_t aBase = smem_u32(As);
    const uint32_t bBase = smem_u32(Bs);
    const uint32_t aoffElem = (uint32_t)((wm * 32 + (lane & 15)) * LDS + (lane >> 4) * 8);
    const uint32_t boffElem = (uint32_t)((wn * 64 + ((lane >> 4) << 3) + (lane & 7)) * LDS +
                                         ((lane >> 3) & 1) * 8);
    const uint32_t cpOff = (uint32_t)(crow * LDS + cseg * 8) * 2;

    auto issue = [&](int nit) {
        const int k0 = nit * 64;
        const int st = nit % NSTAGE;
        const uint32_t sa = aBase + st * STAGE_BYTES + cpOff;
        const uint32_t sb = bBase + st * STAGE_BYTES + cpOff;
        const __half* ga = A + (size_t)(m0 + crow) * lda + k0 + cseg * 8;
        const __half* gb = B + (size_t)(n0 + crow) * ldb + k0 + cseg * 8;
        #pragma unroll
        for (int i = 0; i < 4; i++) cp16(sa + i * 16, ga + i * 8);
        #pragma unroll
        for (int i = 0; i < 4; i++) cp16(sb + i * 16, gb + i * 8);
        cp_commit();
    };

    issue(0);
    if (NT > 1) issue(1);

    for (int it = 0; it < NT; it++) {
        cp_wait<NSTAGE - 2>();
        __syncthreads();

        const int st = it % NSTAGE;
        const uint32_t aB = aBase + st * STAGE_BYTES;
        const uint32_t bB = bBase + st * STAGE_BYTES;

        #pragma unroll
        for (int ks = 0; ks < 4; ks++) {
            const uint32_t kofs = (uint32_t)(ks * 16) * 2;
            uint32_t a[2][4];
            #pragma unroll
            for (int mi = 0; mi < 2; mi++)
                ldsm4(a[mi][0], a[mi][1], a[mi][2], a[mi][3],
                      aB + (aoffElem + (uint32_t)(mi * 16) * LDS) * 2 + kofs);
            uint32_t b[4][4];
            #pragma unroll
            for (int nb = 0; nb < 4; nb++)
                ldsm4(b[nb][0], b[nb][1], b[nb][2], b[nb][3],
                      bB + (boffElem + (uint32_t)(nb * 16) * LDS) * 2 + kofs);
            #pragma unroll
            for (int mi = 0; mi < 2; mi++)
                #pragma unroll
                for (int nb = 0; nb < 4; nb++) {
                    mma16816(acc[mi][nb * 2 + 0], a[mi], b[nb][0], b[nb][1]);
                    mma16816(acc[mi][nb * 2 + 1], a[mi], b[nb][2], b[nb][3]);
                }
        }

        if (it + NSTAGE - 1 < NT) issue(it + NSTAGE - 1);
    }

    // epilogue: write fp16 pairs (half2)
    const int g = lane >> 2, tg = lane & 3;
    #pragma unroll
    for (int mi = 0; mi < 2; mi++) {
        #pragma unroll
        for (int nj = 0; nj < 8; nj++) {
            int col = n0 + wn * 64 + nj * 8 + tg * 2;
            int mrow = m0 + wm * 32 + mi * 16 + g;
            #pragma unroll
            for (int half = 0; half < 2; half++) {
                int r = mrow + half * 8;
                if (r < M && col < Nout) {
                    __half2 v = __floats2half2_rn(acc[mi][nj][half * 2 + 0],
                                                  acc[mi][nj][half * 2 + 1]);
                    if (col + 2 <= Nout) {
                        *(__half2*)(C + (size_t)r * Nout + col) = v;
                    } else {
                        C[(size_t)r * Nout + col] = __low2half(v);
                    }
                }
            }
        }
    }
}

// ---------------------------------------------------------------------------
// Aggregation: out[d] = relu(sum_e h[src]*dinv[s]*dinv[d] + h[d]*dinv[d]^2 + b)
// h fp16, accum fp32, edge loop unrolled x2.
// ---------------------------------------------------------------------------
template <int F, int FPAD>
__global__ __launch_bounds__(128) void k_agg_f16(
    const __half* __restrict__ h, const float* __restrict__ bias,
    __half* __restrict__ out16) {
    constexpr int BLOCK = 128;
    constexpr int PER = (F + BLOCK - 1) / BLOCK;
    const int node = blockIdx.x;
    const int t = threadIdx.x;

    const float di = g_dinv[node];
    const int s0 = g_start[node];
    const int d  = g_deg[node];

    float acc[PER];
    #pragma unroll
    for (int i = 0; i < PER; i++) {
        int f = t + i * BLOCK;
        acc[i] = (f < F) ? __half2float(h[(size_t)node * F + f]) * di * di : 0.f;
    }
    int e = 0;
    for (; e + 2 <= d; e += 2) {
        int s1 = g_csr_src[s0 + e];
        int s2 = g_csr_src[s0 + e + 1];
        float w1 = g_dinv[s1] * di;
        float w2 = g_dinv[s2] * di;
        const __half* r1 = h + (size_t)s1 * F;
        const __half* r2 = h + (size_t)s2 * F;
        #pragma unroll
        for (int i = 0; i < PER; i++) {
            int f = t + i * BLOCK;
            if (f < F) acc[i] += __half2float(r1[f]) * w1 + __half2float(r2[f]) * w2;
        }
    }
    if (e < d) {
        int s = g_csr_src[s0 + e];
        float w = g_dinv[s] * di;
        const __half* r = h + (size_t)s * F;
        #pragma unroll
        for (int i = 0; i < PER; i++) {
            int f = t + i * BLOCK;
            if (f < F) acc[i] += __half2float(r[f]) * w;
        }
    }
    #pragma unroll
    for (int i = 0; i < PER; i++) {
        int f = t + i * BLOCK;
        if (f < F) {
            float v = acc[i] + bias[f];
            v = v > 0.f ? v : 0.f;
            out16[(size_t)node * FPAD + f] = __float2half_rn(v);
        }
    }
    if (FPAD > F && t < FPAD - F)
        out16[(size_t)node * FPAD + F + t] = __float2half_rn(0.f);
}

template <int F>
__global__ __launch_bounds__(128) void k_agg_out(
    const __half* __restrict__ h, const float* __restrict__ bias,
    float* __restrict__ out) {
    constexpr int BLOCK = 128;
    constexpr int PER = (F + BLOCK - 1) / BLOCK;
    const int node = blockIdx.x;
    const int t = threadIdx.x;

    const float di = g_dinv[node];
    const int s0 = g_start[node];
    const int d  = g_deg[node];

    float acc[PER];
    #pragma unroll
    for (int i = 0; i < PER; i++) {
        int f = t + i * BLOCK;
        acc[i] = (f < F) ? __half2float(h[(size_t)node * F + f]) * di * di : 0.f;
    }
    int e = 0;
    for (; e + 2 <= d; e += 2) {
        int s1 = g_csr_src[s0 + e];
        int s2 = g_csr_src[s0 + e + 1];
        float w1 = g_dinv[s1] * di;
        float w2 = g_dinv[s2] * di;
        const __half* r1 = h + (size_t)s1 * F;
        const __half* r2 = h + (size_t)s2 * F;
        #pragma unroll
        for (int i = 0; i < PER; i++) {
            int f = t + i * BLOCK;
            if (f < F) acc[i] += __half2float(r1[f]) * w1 + __half2float(r2[f]) * w2;
        }
    }
    if (e < d) {
        int s = g_csr_src[s0 + e];
        float w = g_dinv[s] * di;
        const __half* r = h + (size_t)s * F;
        #pragma unroll
        for (int i = 0; i < PER; i++) {
            int f = t + i * BLOCK;
            if (f < F) acc[i] += __half2float(r[f]) * w;
        }
    }
    #pragma unroll
    for (int i = 0; i < PER; i++) {
        int f = t + i * BLOCK;
        if (f < F) {
            float v = acc[i] + bias[f];
            out[(size_t)node * F + f] = v > 0.f ? v : 0.f;
        }
    }
}

// ---------------------------------------------------------------------------
// Launch. 4th launch is fp16_gemm layer 1 (ncu capture lands there).
// ---------------------------------------------------------------------------
extern "C" void kernel_launch(void* const* d_in, const int* in_sizes, int n_in,
                              void* d_out, int out_size) {
    const float* x  = (const float*)d_in[0];
    const float* W1 = (const float*)d_in[1];
    const float* b1 = (const float*)d_in[2];
    const float* W2 = (const float*)d_in[3];
    const float* b2 = (const float*)d_in[4];
    const float* W3 = (const float*)d_in[5];
    const float* b3 = (const float*)d_in[6];
    const int*   ei = (const int*)d_in[7];   // int32 (JAX x64-disabled downcast)

    const int D0 = 1280;
    const int N = in_sizes[0] / D0;
    const int E = in_sizes[7] / 2;
    const int* src = ei;
    const int* dst = ei + E;

    __half *h16 = nullptr, *a16 = nullptr, *w1 = nullptr, *w2 = nullptr, *w3 = nullptr;
    cudaGetSymbolAddress((void**)&h16, g_h16);
    cudaGetSymbolAddress((void**)&a16, g_a16);
    cudaGetSymbolAddress((void**)&w1,  g_w1);
    cudaGetSymbolAddress((void**)&w2,  g_w2);
    cudaGetSymbolAddress((void**)&w3,  g_w3);

    const int SMEM_BYTES = NSTAGE * STAGE_BYTES * 2;
    cudaFuncSetAttribute(fp16_gemm, cudaFuncAttributeMaxDynamicSharedMemorySize,
                         SMEM_BYTES);

    const int T = 256;
    const int nbN = (N + T - 1) / T;
    const int nbE = (E + T - 1) / T;
    const int nbScan = (N + 255) / 256;
    const int ntm = MPAD / 128;  // 391
    const int totX = N * D0;

    // 1: x -> fp16
    k_cvt<<<(totX / 4 + 255) / 256, 256>>>(x, a16, totX);
    // 2-3: weight transposes
    k_wt<<<(512 * 1280 + 255) / 256, 256>>>(W1, w1, 1280, 512, 1280, 512);
    k_wt<<<(384 * 512 + 255) / 256, 256>>>(W2, w2, 512, 300, 512, 384);
    // 4: GEMM layer 1 (ncu capture target)
    fp16_gemm<<<dim3(4, ntm), 256, SMEM_BYTES>>>(a16, 1280, w1, 1280, h16, N, 512, 1280);
    // 5: W3
    k_wt<<<(384 * 320 + 255) / 256, 256>>>(W3, w3, 300, 300, 320, 384);
    // 6-11: CSR build + dinv
    k_zero<<<nbN, T>>>(N);
    k_hist<<<nbE, T>>>(dst, E, N);
    k_scan_block<<<nbScan, 256>>>(N);
    k_scan_top<<<1, 256>>>(nbScan);
    k_finish<<<nbN, T>>>(N);
    k_fill<<<nbE, T>>>(src, dst, E, N);

    // Layer 1 aggregation -> fp16 input of layer 2
    k_agg_f16<512, 512><<<N, 128>>>(h16, b1, a16);

    // Layer 2
    fp16_gemm<<<dim3(3, ntm), 256, SMEM_BYTES>>>(a16, 512, w2, 512, h16, N, 300, 512);
    k_agg_f16<300, 320><<<N, 128>>>(h16, b2, a16);

    // Layer 3
    fp16_gemm<<<dim3(3, ntm), 256, SMEM_BYTES>>>(a16, 320, w3, 320, h16, N, 300, 320);
    k_agg_out<300><<<N, 128>>>(h16, b3, (float*)d_out);
}